// round 10
// baseline (speedup 1.0000x reference)
#include <cuda_runtime.h>

#define PI_F 3.14159265358979323846f
#define RS2 0.70710678118654752440f
#define FULL 0xffffffffu

// One warp = exact 7-qubit lightcone of z_q for one (row, qubit).
// Lane bits = (b0,b1,b2,b4,b6); register index j = b3 + 2*b5.
// Prep is split: lanes 0..15 compute x-dependent tables (u, merged-mid RY),
// lanes 16..31 compute x-independent tables (h1, cis h2, end RY) in parallel.
// All table reads are warp-uniform-lane shfl broadcasts — no smem, no barrier.
__global__ __launch_bounds__(128) void qmain(
        const float* __restrict__ x, const float* __restrict__ wcrz,
        const float* __restrict__ wry, const float* __restrict__ scal,
        float* __restrict__ out) {
    int c = blockIdx.x, r = c >> 2;
    int t = threadIdx.x, lane = t & 31, w = t >> 5;
    int q = ((c & 3) << 2) | w;
    int bb = r >> 3, p = r & 7;

    // ---- per-warp prep, one qubit per lane (two register groups) ----
    float rA = 0.f, rB = 0.f, rC = 0.f, rD = 0.f, rE = 0.f;
    int qq = lane & 15;
    if (lane < 16) {
        // x-dependent: u0,u1 (init amps) and merged mid-RY cos/sin
        float xv = x[bb * 128 + (qq >> 2) * 32 + p * 4 + (qq & 3)] * scal[0];
        float ex = __expf(2.f * xv);
        float e = __fdividef(ex - 1.f, ex + 1.f) * PI_F;   // pi * tanh(xv)
        float sh, ch; __sincosf(0.5f * e, &sh, &ch);
        rA = (ch - sh) * RS2;                               // u0
        rB = (ch + sh) * RS2;                               // u1
        float sm_, cm_; __sincosf(0.5f * (wry[qq] + e), &sm_, &cm_);
        rC = cm_; rD = sm_;                                 // mid RY cos/sin
    } else {
        // x-independent: D1 half-angle, cis(D2 half-angle), end RY cos/sin
        rA = 0.5f * wcrz[qq];                               // h1
        float s2, c2; __sincosf(0.5f * wcrz[16 + qq], &s2, &c2);
        rB = c2; rC = s2;                                   // cis h2
        float se_, ce_; __sincosf(0.5f * wry[16 + qq], &se_, &ce_);
        rD = ce_; rE = se_;                                 // end RY cos/sin
    }

    // window qubits: local bit k <-> global qubit q-3+k (mod 16)
    int p0 = (q + 13) & 15, p1 = (q + 14) & 15, p2 = (q + 15) & 15;
    int p4 = (q + 1) & 15,  p5 = (q + 2) & 15,  p6 = (q + 3) & 15;
    int b0 = lane & 1, b1 = (lane >> 1) & 1, b2 = (lane >> 2) & 1;
    int b4 = (lane >> 3) & 1, b6 = (lane >> 4) & 1;

    // ---- shfl broadcasts (warp-uniform source lanes) ----
    float U0x = __shfl_sync(FULL, rA, p0), U0y = __shfl_sync(FULL, rB, p0);
    float U1x = __shfl_sync(FULL, rA, p1), U1y = __shfl_sync(FULL, rB, p1);
    float U2x = __shfl_sync(FULL, rA, p2), U2y = __shfl_sync(FULL, rB, p2);
    float Uqx = __shfl_sync(FULL, rA, q),  Uqy = __shfl_sync(FULL, rB, q);
    float U4x = __shfl_sync(FULL, rA, p4), U4y = __shfl_sync(FULL, rB, p4);
    float U5x = __shfl_sync(FULL, rA, p5), U5y = __shfl_sync(FULL, rB, p5);
    float U6x = __shfl_sync(FULL, rA, p6), U6y = __shfl_sync(FULL, rB, p6);
    float h1p0 = __shfl_sync(FULL, rA, 16 + p0);
    float h1p1 = __shfl_sync(FULL, rA, 16 + p1);
    float h1p2 = __shfl_sync(FULL, rA, 16 + p2);
    float h1q  = __shfl_sync(FULL, rA, 16 + q);
    float h1p4 = __shfl_sync(FULL, rA, 16 + p4);
    float h1p5 = __shfl_sync(FULL, rA, 16 + p5);
    float M1x = __shfl_sync(FULL, rC, p1), M1y = __shfl_sync(FULL, rD, p1);
    float Mqx = __shfl_sync(FULL, rC, q),  Mqy = __shfl_sync(FULL, rD, q);
    float M5x = __shfl_sync(FULL, rC, p5), M5y = __shfl_sync(FULL, rD, p5);
    float Hax = __shfl_sync(FULL, rB, 16 + p1), Hay = __shfl_sync(FULL, rC, 16 + p1);
    float Hbx = __shfl_sync(FULL, rB, 16 + q),  Hby = __shfl_sync(FULL, rC, 16 + q);
    float Ex  = __shfl_sync(FULL, rD, 16 + q),  Ey  = __shfl_sync(FULL, rE, 16 + q);

    // ---- init product amplitude over lane bits ----
    float base = (b0 ? U0y : U0x) * (b1 ? U1y : U1x) * (b2 ? U2y : U2x)
               * (b4 ? U4y : U4x) * (b6 ? U6y : U6x);
    // D1 ring phase: control? (target? +h : -h) : 0 over the 6 window pairs
    float phiL = (b0 ? (b1 ? h1p0 : -h1p0) : 0.f)
               + (b1 ? (b2 ? h1p1 : -h1p1) : 0.f);
    float A0 = b2 ? -h1p2 : 0.f;                               // b3 = 0
    float A1 = (b2 ? h1p2 : 0.f) + (b4 ? h1q : -h1q);          // b3 = 1
    float B0 = b4 ? -h1p4 : 0.f;                               // b5 = 0
    float B1 = (b4 ? h1p4 : 0.f) + (b6 ? h1p5 : -h1p5);        // b5 = 1

    float vr[4], vi[4];
    {
        float ang[4] = { phiL + A0 + B0, phiL + A1 + B0,
                         phiL + A0 + B1, phiL + A1 + B1 };     // j = b3 + 2*b5
        float fj[4] = { base * Uqx * U5x, base * Uqy * U5x,
                        base * Uqx * U5y, base * Uqy * U5y };
#pragma unroll
        for (int j = 0; j < 4; j++) {
            float s_, c_; __sincosf(ang[j], &s_, &c_);
            vr[j] = fj[j] * c_; vi[j] = fj[j] * s_;
        }
    }
    // mid RY on qubit q-2 (lane bit 1): the only shfl gate
    {
        float cc = M1x, sg = b1 ? M1y : -M1y;
#pragma unroll
        for (int j = 0; j < 4; j++) {
            float pr = __shfl_xor_sync(FULL, vr[j], 2);
            float pi = __shfl_xor_sync(FULL, vi[j], 2);
            vr[j] = cc * vr[j] + sg * pr;
            vi[j] = cc * vi[j] + sg * pi;
        }
    }
    // mid RY on qubit q (register bit b3): pairs (0,1),(2,3)
    {
        float cc = Mqx, ss = Mqy;
#pragma unroll
        for (int jj = 0; jj < 4; jj += 2) {
            float r0 = vr[jj], r1 = vr[jj + 1];
            vr[jj] = cc * r0 - ss * r1;  vr[jj + 1] = ss * r0 + cc * r1;
            float i0 = vi[jj], i1 = vi[jj + 1];
            vi[jj] = cc * i0 - ss * i1;  vi[jj + 1] = ss * i0 + cc * i1;
        }
    }
    // mid RY on qubit q+2 (register bit b5): pairs (0,2),(1,3)
    {
        float cc = M5x, ss = M5y;
#pragma unroll
        for (int jj = 0; jj < 2; jj++) {
            float r0 = vr[jj], r1 = vr[jj + 2];
            vr[jj] = cc * r0 - ss * r1;  vr[jj + 2] = ss * r0 + cc * r1;
            float i0 = vi[jj], i1 = vi[jj + 2];
            vi[jj] = cc * i0 - ss * i1;  vi[jj + 2] = ss * i0 + cc * i1;
        }
    }
    // D2 diagonal: CRZ(q-2 -> q) uses (b1,b3); CRZ(q -> q+2) uses (b3,b5)
    {
        float pr0 = b1 ? Hax : 1.f, pi0 = b1 ? -Hay : 0.f;     // b3 = 0 factor
        float prA = pr0,            piA = b1 ?  Hay : 0.f;     // b3 = 1 base
#pragma unroll
        for (int jj = 0; jj < 4; jj += 2) {                    // j = 0, 2 (b3 = 0)
            float nr = vr[jj] * pr0 - vi[jj] * pi0;
            vi[jj] = vr[jj] * pi0 + vi[jj] * pr0;
            vr[jj] = nr;
        }
        float pr1 = prA * Hbx + piA * Hby, pi1 = -prA * Hby + piA * Hbx;
        float pr3 = prA * Hbx - piA * Hby, pi3 =  prA * Hby + piA * Hbx;
        float nr1 = vr[1] * pr1 - vi[1] * pi1;
        vi[1] = vr[1] * pi1 + vi[1] * pr1; vr[1] = nr1;
        float nr3 = vr[3] * pr3 - vi[3] * pi3;
        vi[3] = vr[3] * pi3 + vi[3] * pr3; vr[3] = nr3;
    }
    // end RY on qubit q (register bit b3)
    {
        float cc = Ex, ss = Ey;
#pragma unroll
        for (int jj = 0; jj < 4; jj += 2) {
            float r0 = vr[jj], r1 = vr[jj + 1];
            vr[jj] = cc * r0 - ss * r1;  vr[jj + 1] = ss * r0 + cc * r1;
            float i0 = vi[jj], i1 = vi[jj + 1];
            vi[jj] = cc * i0 - ss * i1;  vi[jj + 1] = ss * i0 + cc * i1;
        }
    }
    // z_q = sum (1 - 2*b3) |amp|^2 ; b3 = j&1
    float acc = (vr[0] * vr[0] + vi[0] * vi[0]) - (vr[1] * vr[1] + vi[1] * vi[1])
              + (vr[2] * vr[2] + vi[2] * vi[2]) - (vr[3] * vr[3] + vi[3] * vi[3]);
#pragma unroll
    for (int o = 16; o > 0; o >>= 1) acc += __shfl_down_sync(FULL, acc, o);
    if (lane == 0)
        out[bb * 128 + (q >> 2) * 32 + p * 4 + (q & 3)] = fminf(1.f, fmaxf(-1.f, acc));
}

extern "C" void kernel_launch(void* const* d_in, const int* in_sizes, int n_in,
                              void* d_out, int out_size) {
    const float* x    = (const float*)d_in[0];
    const float* wcrz = (const float*)d_in[1];
    const float* wry  = (const float*)d_in[2];
    const float* sc   = (const float*)d_in[3];
    (void)in_sizes; (void)n_in; (void)out_size;
    qmain<<<256, 128>>>(x, wcrz, wry, sc, (float*)d_out);
}

// round 11
// speedup vs baseline: 1.0386x; 1.0386x over previous
#include <cuda_runtime.h>

#define PI_F 3.14159265358979323846f
#define RS2 0.70710678118654752440f
#define FULL 0xffffffffu

// One warp = exact 7-qubit lightcone of z_q for one (row, qubit).
// Lane bits = (b0,b1,b2,b4,b6); register index j = b3 + 2*b5.
// Geometry: CTA = one row (16 warps = 16 qubits), grid = 64 rows.
// Per-warp redundant prep, split across half-warps:
//   lanes 0..15  -> x-dependent tables (init amps u, merged mid-RY)
//   lanes 16..31 -> x-independent tables (h1, cis h2, end RY), concurrent
//                   with the LDG(x)->tanh->sincos chain in the low lanes.
// Tables land in per-warp smem; all reads are warp-broadcast LDS. No CTA barrier.
__global__ __launch_bounds__(512) void qmain(
        const float* __restrict__ x, const float* __restrict__ wcrz,
        const float* __restrict__ wry, const float* __restrict__ scal,
        float* __restrict__ out) {
    __shared__ float2 Wu[16][16];   // (u0,u1): init amps RY(enc)·H|0>
    __shared__ float2 Wm[16][16];   // (cos,sin) merged mid RY (w0+enc)/2
    __shared__ float  Wh1[16][16];  // layer-0 CRZ half-angle
    __shared__ float2 Wh2[16][16];  // cis(layer-1 CRZ half-angle)
    __shared__ float2 We[16][16];   // (cos,sin) end RY w1/2

    int r = blockIdx.x;
    int t = threadIdx.x, lane = t & 31, w = t >> 5;
    int q = w;
    int bb = r >> 3, p = r & 7;

    int qq = lane & 15;
    if (lane < 16) {
        // x-dependent chain
        float xv = x[bb * 128 + (qq >> 2) * 32 + p * 4 + (qq & 3)] * scal[0];
        float ex = __expf(2.f * xv);
        float e = __fdividef(ex - 1.f, ex + 1.f) * PI_F;   // pi * tanh(xv)
        float sh, ch; __sincosf(0.5f * e, &sh, &ch);
        Wu[w][qq] = make_float2((ch - sh) * RS2, (ch + sh) * RS2);
        float sm_, cm_; __sincosf(0.5f * (wry[qq] + e), &sm_, &cm_);
        Wm[w][qq] = make_float2(cm_, sm_);
    } else {
        // x-independent, runs concurrently with the low half-warp
        Wh1[w][qq] = 0.5f * wcrz[qq];
        float s2, c2; __sincosf(0.5f * wcrz[16 + qq], &s2, &c2);
        Wh2[w][qq] = make_float2(c2, s2);
        float se_, ce_; __sincosf(0.5f * wry[16 + qq], &se_, &ce_);
        We[w][qq] = make_float2(ce_, se_);
    }
    __syncwarp();

    // window qubits: local bit k <-> global qubit q-3+k (mod 16)
    int p0 = (q + 13) & 15, p1 = (q + 14) & 15, p2 = (q + 15) & 15;
    int p4 = (q + 1) & 15,  p5 = (q + 2) & 15,  p6 = (q + 3) & 15;
    int b0 = lane & 1, b1 = (lane >> 1) & 1, b2 = (lane >> 2) & 1;
    int b4 = (lane >> 3) & 1, b6 = (lane >> 4) & 1;

    // warp-broadcast smem reads
    float2 U0 = Wu[w][p0], U1 = Wu[w][p1], U2 = Wu[w][p2];
    float2 Uq = Wu[w][q],  U4 = Wu[w][p4], U5 = Wu[w][p5], U6 = Wu[w][p6];
    float h1p0 = Wh1[w][p0], h1p1 = Wh1[w][p1], h1p2 = Wh1[w][p2];
    float h1q = Wh1[w][q], h1p4 = Wh1[w][p4], h1p5 = Wh1[w][p5];
    float2 M1 = Wm[w][p1], Mq = Wm[w][q], M5 = Wm[w][p5];
    float2 Ha = Wh2[w][p1], Hb = Wh2[w][q];
    float2 E = We[w][q];

    // init product amplitude over lane bits
    float base = (b0 ? U0.y : U0.x) * (b1 ? U1.y : U1.x) * (b2 ? U2.y : U2.x)
               * (b4 ? U4.y : U4.x) * (b6 ? U6.y : U6.x);
    // D1 ring phase: control? (target? +h : -h) : 0 over the 6 window pairs
    float phiL = (b0 ? (b1 ? h1p0 : -h1p0) : 0.f)
               + (b1 ? (b2 ? h1p1 : -h1p1) : 0.f);
    float A0 = b2 ? -h1p2 : 0.f;                               // b3 = 0
    float A1 = (b2 ? h1p2 : 0.f) + (b4 ? h1q : -h1q);          // b3 = 1
    float B0 = b4 ? -h1p4 : 0.f;                               // b5 = 0
    float B1 = (b4 ? h1p4 : 0.f) + (b6 ? h1p5 : -h1p5);        // b5 = 1

    float vr[4], vi[4];
    {
        float ang[4] = { phiL + A0 + B0, phiL + A1 + B0,
                         phiL + A0 + B1, phiL + A1 + B1 };     // j = b3 + 2*b5
        float fj[4] = { base * Uq.x * U5.x, base * Uq.y * U5.x,
                        base * Uq.x * U5.y, base * Uq.y * U5.y };
#pragma unroll
        for (int j = 0; j < 4; j++) {
            float s_, c_; __sincosf(ang[j], &s_, &c_);
            vr[j] = fj[j] * c_; vi[j] = fj[j] * s_;
        }
    }
    // mid RY on qubit q-2 (lane bit 1): the only shfl gate
    {
        float cc = M1.x, sg = b1 ? M1.y : -M1.y;
#pragma unroll
        for (int j = 0; j < 4; j++) {
            float pr = __shfl_xor_sync(FULL, vr[j], 2);
            float pi = __shfl_xor_sync(FULL, vi[j], 2);
            vr[j] = cc * vr[j] + sg * pr;
            vi[j] = cc * vi[j] + sg * pi;
        }
    }
    // mid RY on qubit q (register bit b3): pairs (0,1),(2,3)
    {
        float cc = Mq.x, ss = Mq.y;
#pragma unroll
        for (int jj = 0; jj < 4; jj += 2) {
            float r0 = vr[jj], r1 = vr[jj + 1];
            vr[jj] = cc * r0 - ss * r1;  vr[jj + 1] = ss * r0 + cc * r1;
            float i0 = vi[jj], i1 = vi[jj + 1];
            vi[jj] = cc * i0 - ss * i1;  vi[jj + 1] = ss * i0 + cc * i1;
        }
    }
    // mid RY on qubit q+2 (register bit b5): pairs (0,2),(1,3)
    {
        float cc = M5.x, ss = M5.y;
#pragma unroll
        for (int jj = 0; jj < 2; jj++) {
            float r0 = vr[jj], r1 = vr[jj + 2];
            vr[jj] = cc * r0 - ss * r1;  vr[jj + 2] = ss * r0 + cc * r1;
            float i0 = vi[jj], i1 = vi[jj + 2];
            vi[jj] = cc * i0 - ss * i1;  vi[jj + 2] = ss * i0 + cc * i1;
        }
    }
    // D2 diagonal: CRZ(q-2 -> q) uses (b1,b3); CRZ(q -> q+2) uses (b3,b5)
    {
        float pr0 = b1 ? Ha.x : 1.f, pi0 = b1 ? -Ha.y : 0.f;   // b3 = 0 factor
        float prA = pr0,            piA = b1 ?  Ha.y : 0.f;    // b3 = 1 base
#pragma unroll
        for (int jj = 0; jj < 4; jj += 2) {                    // j = 0, 2 (b3 = 0)
            float nr = vr[jj] * pr0 - vi[jj] * pi0;
            vi[jj] = vr[jj] * pi0 + vi[jj] * pr0;
            vr[jj] = nr;
        }
        float pr1 = prA * Hb.x + piA * Hb.y, pi1 = -prA * Hb.y + piA * Hb.x;
        float pr3 = prA * Hb.x - piA * Hb.y, pi3 =  prA * Hb.y + piA * Hb.x;
        float nr1 = vr[1] * pr1 - vi[1] * pi1;
        vi[1] = vr[1] * pi1 + vi[1] * pr1; vr[1] = nr1;
        float nr3 = vr[3] * pr3 - vi[3] * pi3;
        vi[3] = vr[3] * pi3 + vi[3] * pr3; vr[3] = nr3;
    }
    // end RY on qubit q (register bit b3)
    {
        float cc = E.x, ss = E.y;
#pragma unroll
        for (int jj = 0; jj < 4; jj += 2) {
            float r0 = vr[jj], r1 = vr[jj + 1];
            vr[jj] = cc * r0 - ss * r1;  vr[jj + 1] = ss * r0 + cc * r1;
            float i0 = vi[jj], i1 = vi[jj + 1];
            vi[jj] = cc * i0 - ss * i1;  vi[jj + 1] = ss * i0 + cc * i1;
        }
    }
    // z_q = sum (1 - 2*b3) |amp|^2 ; b3 = j&1
    float acc = (vr[0] * vr[0] + vi[0] * vi[0]) - (vr[1] * vr[1] + vi[1] * vi[1])
              + (vr[2] * vr[2] + vi[2] * vi[2]) - (vr[3] * vr[3] + vi[3] * vi[3]);
#pragma unroll
    for (int o = 16; o > 0; o >>= 1) acc += __shfl_down_sync(FULL, acc, o);
    if (lane == 0)
        out[bb * 128 + (q >> 2) * 32 + p * 4 + (q & 3)] = fminf(1.f, fmaxf(-1.f, acc));
}

extern "C" void kernel_launch(void* const* d_in, const int* in_sizes, int n_in,
                              void* d_out, int out_size) {
    const float* x    = (const float*)d_in[0];
    const float* wcrz = (const float*)d_in[1];
    const float* wry  = (const float*)d_in[2];
    const float* sc   = (const float*)d_in[3];
    (void)in_sizes; (void)n_in; (void)out_size;
    qmain<<<64, 512>>>(x, wcrz, wry, sc, (float*)d_out);
}